// round 14
// baseline (speedup 1.0000x reference)
#include <cuda_runtime.h>
#include <cuda_bf16.h>
#include <cstdint>

// ---------------------------------------------------------------------------
// Problem constants
// ---------------------------------------------------------------------------
#define NN     100000
#define NE     600000
#define NCEN   512
#define NMOLN  20000
#define NRELS  50
#define D      128
#define NMOT   85

#define OFF_MOTIF (NE * 50)
#define OFF_NODE  (OFF_MOTIF + NCEN * NMOT)
#define OFF_BIN   (OFF_NODE + NMOLN * 15)

// ---------------------------------------------------------------------------
// Device scratch
// ---------------------------------------------------------------------------
__device__ float g_xn   [NN * D];
__device__ float g_x0   [NN * D];
__device__ float g_x1   [NN * D];
__device__ float g_agg  [NN * D];
__device__ float g_elin [NRELS * D];
__device__ float g_proj [NN * 116];
__device__ float g_Wcat [D * 116];
__device__ float g_bcat [116];
__device__ float g_Wfold[D * 116];    // W2 @ Wcat
__device__ float g_bfold[116];        // b2 @ Wcat + bcat
__device__ float g_Wmot [D * NMOT];   // W2 @ motif_W
__device__ float g_bmot [NMOT];       // b2 @ motif_W + motif_b

// ---------------------------------------------------------------------------
// bf16 helpers
// ---------------------------------------------------------------------------
__device__ __forceinline__ uint32_t pack_bf2(float a, float b) {
    __nv_bfloat162 h(__float2bfloat16_rn(a), __float2bfloat16_rn(b));
    return *reinterpret_cast<uint32_t*>(&h);
}
__device__ __forceinline__ float bf_hi(float a) {
    return __bfloat162float(__float2bfloat16_rn(a));
}

// mma.sync m16n8k16 row.col f32.bf16.bf16.f32
#define MMA_BF16(c, a, b0, b1) \
    asm("mma.sync.aligned.m16n8k16.row.col.f32.bf16.bf16.f32 " \
        "{%0,%1,%2,%3}, {%4,%5,%6,%7}, {%8,%9}, {%0,%1,%2,%3};" \
        : "+f"((c)[0]), "+f"((c)[1]), "+f"((c)[2]), "+f"((c)[3]) \
        : "r"((a)[0]), "r"((a)[1]), "r"((a)[2]), "r"((a)[3]), \
          "r"(b0), "r"(b1))

// ---------------------------------------------------------------------------
// HMMA GEMM (proven): Y[r,c] = act( A@W + b ),  K=128, C<=128.
// 3-term bf16 split (ah*bh + ah*bl + al*bh) ~ fp32 accuracy.
// CTA 256 thr = 8 warps (4 row x 2 col), tile 128x128; warp 32x64.
// AMODE: 0 = A1 ; 1 = A1+A2
// ---------------------------------------------------------------------------
#define PK 68   // b32 words per staged row (64 data + 4 pad)

template <int C, bool RELU, int AMODE>
__global__ __launch_bounds__(256, 1)
void hgemm_k(const float* __restrict__ A1, const float* __restrict__ A2,
             const int* __restrict__ ridx, int nrows,
             const float* __restrict__ W, const float* __restrict__ bias,
             float* __restrict__ Y) {
    extern __shared__ __align__(16) uint32_t sm32[];
    uint32_t* sAh = sm32;                  // [128][PK]
    uint32_t* sAl = sAh + 128 * PK;
    uint32_t* sBh = sAl + 128 * PK;        // [n][PK] = W^T packed k-pairs
    uint32_t* sBl = sBh + 128 * PK;
    float*  sBias = (float*)(sBl + 128 * PK);   // 128

    const int tid = threadIdx.x;
    const int r0 = blockIdx.x * 128;

    if (tid < 128) sBias[tid] = (tid < C) ? bias[tid] : 0.0f;

    // ---- stage A (hi/lo): 128 rows x 32 float4 ----
    for (int i = tid; i < 128 * 32; i += 256) {
        int r = i >> 5, j = i & 31;
        int gr = r0 + r;
        float4 v = make_float4(0.f, 0.f, 0.f, 0.f);
        if (gr < nrows) {
            if (AMODE == 0) {
                v = reinterpret_cast<const float4*>(A1 + (size_t)gr * D)[j];
            } else {
                float4 a = reinterpret_cast<const float4*>(A1 + (size_t)gr * D)[j];
                float4 b = reinterpret_cast<const float4*>(A2 + (size_t)gr * D)[j];
                v = make_float4(a.x + b.x, a.y + b.y, a.z + b.z, a.w + b.w);
            }
        }
        uint2 hh, ll;
        hh.x = pack_bf2(v.x, v.y);
        hh.y = pack_bf2(v.z, v.w);
        ll.x = pack_bf2(v.x - bf_hi(v.x), v.y - bf_hi(v.y));
        ll.y = pack_bf2(v.z - bf_hi(v.z), v.w - bf_hi(v.w));
        *reinterpret_cast<uint2*>(sAh + r * PK + 2 * j) = hh;
        *reinterpret_cast<uint2*>(sAl + r * PK + 2 * j) = ll;
    }

    // ---- stage B = W^T (hi/lo): sB[n][kp] = (W[2kp][n], W[2kp+1][n]) ----
    for (int i = tid; i < 64 * 128; i += 256) {
        int kp = i >> 7, n = i & 127;   // coalesced along n
        float w0 = 0.f, w1 = 0.f;
        if (n < C) {
            w0 = W[(2 * kp) * C + n];
            w1 = W[(2 * kp + 1) * C + n];
        }
        sBh[n * PK + kp] = pack_bf2(w0, w1);
        sBl[n * PK + kp] = pack_bf2(w0 - bf_hi(w0), w1 - bf_hi(w1));
    }
    __syncthreads();

    // ---- mainloop ----
    const int lane = tid & 31, wid = tid >> 5;
    const int g = lane >> 2, tg = lane & 3;
    const int wm = wid & 3, wn = wid >> 2;

    float acc[2][8][4];
#pragma unroll
    for (int mt = 0; mt < 2; mt++)
#pragma unroll
        for (int nt = 0; nt < 8; nt++)
#pragma unroll
            for (int j = 0; j < 4; j++) acc[mt][nt][j] = 0.f;

    const uint32_t* pA = sAh + (wm * 32 + g) * PK;   // sAl = pA + 128*PK
    const uint32_t* pB = sBh + (wn * 64 + g) * PK;   // sBl = pB + 128*PK

#pragma unroll
    for (int ks = 0; ks < 8; ks++) {
        const int kb = ks * 8 + tg;
        uint32_t ah[2][4], al[2][4];
#pragma unroll
        for (int mt = 0; mt < 2; mt++) {
            const uint32_t* ba = pA + mt * 16 * PK;
            ah[mt][0] = ba[kb];
            ah[mt][1] = ba[8 * PK + kb];
            ah[mt][2] = ba[kb + 4];
            ah[mt][3] = ba[8 * PK + kb + 4];
            const uint32_t* bl_ = ba + 128 * PK;
            al[mt][0] = bl_[kb];
            al[mt][1] = bl_[8 * PK + kb];
            al[mt][2] = bl_[kb + 4];
            al[mt][3] = bl_[8 * PK + kb + 4];
        }
#pragma unroll
        for (int np = 0; np < 4; np++) {
            const int n0 = 2 * np, n1 = 2 * np + 1;
            const uint32_t* bb0 = pB + n0 * 8 * PK;
            const uint32_t* bb1 = pB + n1 * 8 * PK;
            uint32_t bh00 = bb0[kb], bh01 = bb0[kb + 4];
            uint32_t bh10 = bb1[kb], bh11 = bb1[kb + 4];
            uint32_t bl00 = bb0[128 * PK + kb], bl01 = bb0[128 * PK + kb + 4];
            uint32_t bl10 = bb1[128 * PK + kb], bl11 = bb1[128 * PK + kb + 4];

            MMA_BF16(acc[0][n0], ah[0], bh00, bh01);
            MMA_BF16(acc[1][n0], ah[1], bh00, bh01);
            MMA_BF16(acc[0][n1], ah[0], bh10, bh11);
            MMA_BF16(acc[1][n1], ah[1], bh10, bh11);

            MMA_BF16(acc[0][n0], ah[0], bl00, bl01);
            MMA_BF16(acc[1][n0], ah[1], bl00, bl01);
            MMA_BF16(acc[0][n1], ah[0], bl10, bl11);
            MMA_BF16(acc[1][n1], ah[1], bl10, bl11);

            MMA_BF16(acc[0][n0], al[0], bh00, bh01);
            MMA_BF16(acc[1][n0], al[1], bh00, bh01);
            MMA_BF16(acc[0][n1], al[0], bh10, bh11);
            MMA_BF16(acc[1][n1], al[1], bh10, bh11);
        }
    }

    // ---- epilogue: direct global stores (float2 only when C even) ----
#pragma unroll
    for (int mt = 0; mt < 2; mt++) {
#pragma unroll
        for (int nt = 0; nt < 8; nt++) {
            int col = wn * 64 + nt * 8 + tg * 2;
            if (col >= C) continue;
            float b0 = sBias[col];
            float b1 = (col + 1 < C) ? sBias[col + 1] : 0.f;
#pragma unroll
            for (int h = 0; h < 2; h++) {
                int row = r0 + wm * 32 + mt * 16 + g + h * 8;
                if (row >= nrows) continue;
                float v0 = acc[mt][nt][2 * h + 0] + b0;
                float v1 = acc[mt][nt][2 * h + 1] + b1;
                if (RELU) { v0 = fmaxf(v0, 0.f); v1 = fmaxf(v1, 0.f); }
                float* yr = Y + (size_t)row * C + col;
                if ((C & 1) == 0 && col + 1 < C) {
                    *reinterpret_cast<float2*>(yr) = make_float2(v0, v1);
                } else {
                    yr[0] = v0;
                    if (col + 1 < C) yr[1] = v1;
                }
            }
        }
    }
}

static constexpr int SMEM_HGEMM = (4 * 128 * PK) * 4 + 512;

// ---------------------------------------------------------------------------
// Small-row GEMM: one warp per output row, fp32 exact, K=128, C<=128.
// MODE 0: A = l2norm(A1[row])            (rel-feature path, ridx unused)
// MODE 1: A = A1[ridx[row]] + A2[ridx[row]]  (motif path)
// Lane holds 4 A-values; k broadcast via shfl; cols split across lanes so
// W loads are coalesced (W <= 64KB -> L1-resident).
// ---------------------------------------------------------------------------
template <int C, bool RELU, int MODE>
__global__ void sgemm_k(const float* __restrict__ A1, const float* __restrict__ A2,
                        const int* __restrict__ ridx, int n,
                        const float* __restrict__ W, const float* __restrict__ bias,
                        float* __restrict__ Y) {
    int row = (blockIdx.x * blockDim.x + threadIdx.x) >> 5;
    if (row >= n) return;
    int lane = threadIdx.x & 31;
    int gidx = (MODE == 1) ? __ldg(ridx + row) : row;

    float a[4];
#pragma unroll
    for (int j = 0; j < 4; j++) {
        float v = A1[(size_t)gidx * D + lane + 32 * j];
        if (MODE == 1) v += A2[(size_t)gidx * D + lane + 32 * j];
        a[j] = v;
    }
    if (MODE == 0) {
        float ss = a[0] * a[0] + a[1] * a[1] + a[2] * a[2] + a[3] * a[3];
#pragma unroll
        for (int o = 16; o; o >>= 1) ss += __shfl_xor_sync(0xffffffffu, ss, o);
        float inv = 1.0f / fmaxf(sqrtf(ss), 1e-12f);
        a[0] *= inv; a[1] *= inv; a[2] *= inv; a[3] *= inv;
    }

    constexpr int NC = (C + 31) / 32;
    float acc[NC];
#pragma unroll
    for (int jc = 0; jc < NC; jc++) acc[jc] = 0.f;

    for (int k = 0; k < 128; k++) {
        float ak = __shfl_sync(0xffffffffu, a[k >> 5], k & 31);
        const float* wr = W + k * C;
#pragma unroll
        for (int jc = 0; jc < NC; jc++) {
            int c = lane + 32 * jc;
            if (c < C) acc[jc] += ak * __ldg(wr + c);
        }
    }

#pragma unroll
    for (int jc = 0; jc < NC; jc++) {
        int c = lane + 32 * jc;
        if (c < C) {
            float v = acc[jc] + bias[c];
            if (RELU) v = fmaxf(v, 0.f);
            Y[(size_t)row * C + c] = v;
        }
    }
}

// ---------------------------------------------------------------------------
// Gather + L2-normalize rows (one warp per row) — node features.
// ---------------------------------------------------------------------------
__global__ void norm_gather_k(const float* __restrict__ table,
                              const int* __restrict__ ids, int n,
                              float* __restrict__ out) {
    int w = (blockIdx.x * blockDim.x + threadIdx.x) >> 5;
    if (w >= n) return;
    int lane = threadIdx.x & 31;
    int g = ids ? ids[w] : w;
    float4 v = reinterpret_cast<const float4*>(table + (size_t)g * D)[lane];
    float ss = v.x * v.x + v.y * v.y + v.z * v.z + v.w * v.w;
#pragma unroll
    for (int o = 16; o; o >>= 1) ss += __shfl_xor_sync(0xffffffffu, ss, o);
    float inv = 1.0f / fmaxf(sqrtf(ss), 1e-12f);
    v.x *= inv; v.y *= inv; v.z *= inv; v.w *= inv;
    reinterpret_cast<float4*>(out + (size_t)w * D)[lane] = v;
}

// ---------------------------------------------------------------------------
// Message pass: agg[dst] += relu(X[src] + Elin[rel]).  One warp per edge.
// Scatter + RED.v4 (confirmed optimal vs CSR gather [R8] and materialize [R11]).
// ---------------------------------------------------------------------------
__global__ void msg_k(const float* __restrict__ X, const float* __restrict__ Elin,
                      const int* __restrict__ src, const int* __restrict__ dst,
                      const int* __restrict__ rel, float* __restrict__ agg, int nE) {
    int w = (blockIdx.x * blockDim.x + threadIdx.x) >> 5;
    if (w >= nE) return;
    int lane = threadIdx.x & 31;
    int s = __ldg(src + w), d = __ldg(dst + w), r = __ldg(rel + w);
    float4 a = reinterpret_cast<const float4*>(X + (size_t)s * D)[lane];
    float4 b = reinterpret_cast<const float4*>(Elin + (size_t)r * D)[lane];
    float4 m;
    m.x = fmaxf(a.x + b.x, 0.0f);
    m.y = fmaxf(a.y + b.y, 0.0f);
    m.z = fmaxf(a.z + b.z, 0.0f);
    m.w = fmaxf(a.w + b.w, 0.0f);
    atomicAdd(reinterpret_cast<float4*>(agg + (size_t)d * D) + lane, m);
}

__global__ void zero_k(float4* __restrict__ p, int n4) {
    int i = blockIdx.x * blockDim.x + threadIdx.x;
    if (i < n4) p[i] = make_float4(0.f, 0.f, 0.f, 0.f);
}

__global__ void pack_k(const float* __restrict__ eW, const float* __restrict__ ncW,
                       const float* __restrict__ bW, const float* __restrict__ eb,
                       const float* __restrict__ ncb, const float* __restrict__ bb,
                       float* __restrict__ Wcat, float* __restrict__ bcat) {
    int i = blockIdx.x * blockDim.x + threadIdx.x;
    if (i < 128 * 116) {
        int k = i / 116, c = i - k * 116;
        float v;
        if (c < 50)       v = eW[k * 50 + c];
        else if (c < 100) v = eW[(128 + k) * 50 + (c - 50)];
        else if (c < 115) v = ncW[k * 15 + (c - 100)];
        else              v = bW[k];
        Wcat[i] = v;
    }
    if (i < 116) {
        float v;
        if (i < 50)       v = eb[i];
        else if (i < 100) v = 0.0f;
        else if (i < 115) v = ncb[i - 100];
        else              v = bb[0];
        bcat[i] = v;
    }
}

// ---------------------------------------------------------------------------
// Linear-head folding (GINE-2 has no ReLU, so W2 composes with all heads):
//   Wfold = W2 @ Wcat ; bfold = b2 @ Wcat + bcat
//   Wmot  = W2 @ motif_W ; bmot = b2 @ motif_W + motif_b
// ---------------------------------------------------------------------------
#define FOLD_TOTAL (128 * 116 + 116 + 128 * NMOT + NMOT)

__global__ void fold_k(const float* __restrict__ W2, const float* __restrict__ b2,
                       const float* __restrict__ Wcat, const float* __restrict__ bcat,
                       const float* __restrict__ motW, const float* __restrict__ motb,
                       float* __restrict__ Wfold, float* __restrict__ bfold,
                       float* __restrict__ Wmot, float* __restrict__ bmot) {
    int id = blockIdx.x * blockDim.x + threadIdx.x;
    if (id < 128 * 116) {
        int i = id / 116, c = id - i * 116;
        float s = 0.f;
#pragma unroll 4
        for (int j = 0; j < 128; j++) s += W2[i * 128 + j] * Wcat[j * 116 + c];
        Wfold[id] = s;
    } else if (id < 128 * 116 + 116) {
        int c = id - 128 * 116;
        float s = bcat[c];
        for (int j = 0; j < 128; j++) s += b2[j] * Wcat[j * 116 + c];
        bfold[c] = s;
    } else if (id < 128 * 116 + 116 + 128 * NMOT) {
        int t = id - (128 * 116 + 116);
        int i = t / NMOT, m = t - i * NMOT;
        float s = 0.f;
#pragma unroll 4
        for (int j = 0; j < 128; j++) s += W2[i * 128 + j] * motW[j * NMOT + m];
        Wmot[t] = s;
    } else if (id < FOLD_TOTAL) {
        int m = id - (128 * 116 + 116 + 128 * NMOT);
        float s = motb[m];
        for (int j = 0; j < 128; j++) s += b2[j] * motW[j * NMOT + m];
        bmot[m] = s;
    }
}

__global__ void edge_out_k(const float* __restrict__ proj, const int* __restrict__ src,
                           const int* __restrict__ dst, float* __restrict__ out) {
    int i = blockIdx.x * blockDim.x + threadIdx.x;
    if (i >= NE * 25) return;
    int e = i / 25, j = i - e * 25;
    int c = j * 2;
    int s = __ldg(src + e), d = __ldg(dst + e);
    float2 p1 = *reinterpret_cast<const float2*>(proj + (size_t)s * 116 + c);
    float2 p2 = *reinterpret_cast<const float2*>(proj + (size_t)d * 116 + 50 + c);
    *reinterpret_cast<float2*>(out + (size_t)e * 50 + c) =
        make_float2(p1.x + p2.x, p1.y + p2.y);
}

__global__ void node_out_k(const float* __restrict__ proj, const int* __restrict__ ids,
                           float* __restrict__ out) {
    int i = blockIdx.x * blockDim.x + threadIdx.x;
    if (i >= NMOLN * 15) return;
    int m = i / 15, c = i - m * 15;
    out[i] = proj[(size_t)__ldg(ids + m) * 116 + 100 + c];
}

__global__ void bin_out_k(const float* __restrict__ proj, float* __restrict__ out) {
    int n = blockIdx.x * blockDim.x + threadIdx.x;
    if (n < NN) out[n] = proj[(size_t)n * 116 + 115];
}

// ---------------------------------------------------------------------------
// Launch
// ---------------------------------------------------------------------------
static inline int cdiv(long long a, long long b) { return (int)((a + b - 1) / b); }

extern "C" void kernel_launch(void* const* d_in, const int* in_sizes, int n_in,
                              void* d_out, int out_size) {
    const int*   node_ids = (const int*)d_in[0];
    const int*   rel_ids  = (const int*)d_in[1];
    const int*   center   = (const int*)d_in[2];
    const int*   nonmol   = (const int*)d_in[3];
    const int*   eidx     = (const int*)d_in[4];
    const float* node_emb = (const float*)d_in[5];
    const float* rel_emb  = (const float*)d_in[6];
    const float* lin_W    = (const float*)d_in[7];
    const float* lin_b    = (const float*)d_in[8];
    const float* W1       = (const float*)d_in[9];
    const float* b1       = (const float*)d_in[10];
    const float* W2       = (const float*)d_in[11];
    const float* b2       = (const float*)d_in[12];
    const float* edge_W   = (const float*)d_in[13];
    const float* edge_b   = (const float*)d_in[14];
    const float* motif_W  = (const float*)d_in[15];
    const float* motif_b  = (const float*)d_in[16];
    const float* nodec_W  = (const float*)d_in[17];
    const float* nodec_b  = (const float*)d_in[18];
    const float* bin_W    = (const float*)d_in[19];
    const float* bin_b    = (const float*)d_in[20];
    const int* src = eidx;
    const int* dst = eidx + NE;
    float* out = (float*)d_out;

    float *xn, *x0, *x1, *agg, *elin, *proj, *Wcat, *bcat;
    float *Wfold, *bfold, *Wmot, *bmot;
    cudaGetSymbolAddress((void**)&xn,    g_xn);
    cudaGetSymbolAddress((void**)&x0,    g_x0);
    cudaGetSymbolAddress((void**)&x1,    g_x1);
    cudaGetSymbolAddress((void**)&agg,   g_agg);
    cudaGetSymbolAddress((void**)&elin,  g_elin);
    cudaGetSymbolAddress((void**)&proj,  g_proj);
    cudaGetSymbolAddress((void**)&Wcat,  g_Wcat);
    cudaGetSymbolAddress((void**)&bcat,  g_bcat);
    cudaGetSymbolAddress((void**)&Wfold, g_Wfold);
    cudaGetSymbolAddress((void**)&bfold, g_bfold);
    cudaGetSymbolAddress((void**)&Wmot,  g_Wmot);
    cudaGetSymbolAddress((void**)&bmot,  g_bmot);

    cudaFuncSetAttribute(hgemm_k<128, true,  0>, cudaFuncAttributeMaxDynamicSharedMemorySize, SMEM_HGEMM);
    cudaFuncSetAttribute(hgemm_k<128, true,  1>, cudaFuncAttributeMaxDynamicSharedMemorySize, SMEM_HGEMM);
    cudaFuncSetAttribute(hgemm_k<116, false, 1>, cudaFuncAttributeMaxDynamicSharedMemorySize, SMEM_HGEMM);

    const int n4 = NN * D / 4;
    const int gN = cdiv(NN, 128);

    // 1) pack output-head weights, then fold W2 into the linear heads
    pack_k<<<cdiv(128 * 116, 256), 256>>>(edge_W, nodec_W, bin_W, edge_b, nodec_b, bin_b,
                                          Wcat, bcat);
    fold_k<<<cdiv(FOLD_TOTAL, 256), 256>>>(W2, b2, Wcat, bcat, motif_W, motif_b,
                                           Wfold, bfold, Wmot, bmot);
    // 2) rel features: fused l2norm + linear + relu (warp per row, fp32)
    sgemm_k<128, true, 0><<<cdiv((long long)NRELS * 32, 256), 256>>>(
        rel_emb, nullptr, nullptr, NRELS, lin_W, lin_b, elin);
    // 3) node features
    norm_gather_k<<<cdiv((long long)NN * 32, 256), 256>>>(node_emb, node_ids, NN, xn);
    hgemm_k<128, true, 0><<<gN, 256, SMEM_HGEMM>>>(xn, nullptr, nullptr, NN,
                                                   lin_W, lin_b, x0);
    // 4) GINE layer 1
    zero_k<<<cdiv(n4, 256), 256>>>((float4*)agg, n4);
    msg_k<<<cdiv((long long)NE * 32, 256), 256>>>(x0, elin, src, dst, rel_ids, agg, NE);
    hgemm_k<128, true, 1><<<gN, 256, SMEM_HGEMM>>>(x0, agg, nullptr, NN, W1, b1, x1);
    // 5) GINE layer 2 message pass (x2 GEMM folded away)
    zero_k<<<cdiv(n4, 256), 256>>>((float4*)agg, n4);
    msg_k<<<cdiv((long long)NE * 32, 256), 256>>>(x1, elin, src, dst, rel_ids, agg, NE);
    // 6) fused projection directly from (x1+agg) via folded weights
    hgemm_k<116, false, 1><<<gN, 256, SMEM_HGEMM>>>(x1, agg, nullptr, NN,
                                                    Wfold, bfold, proj);
    // 7) outputs
    edge_out_k<<<cdiv((long long)NE * 25, 256), 256>>>(proj, src, dst, out);
    sgemm_k<85, false, 1><<<cdiv((long long)NCEN * 32, 256), 256>>>(
        x1, agg, center, NCEN, Wmot, bmot, out + OFF_MOTIF);
    node_out_k<<<cdiv((long long)NMOLN * 15, 256), 256>>>(proj, nonmol, out + OFF_NODE);
    bin_out_k<<<cdiv(NN, 256), 256>>>(proj, out + OFF_BIN);
}

// round 15
// speedup vs baseline: 1.0396x; 1.0396x over previous
#include <cuda_runtime.h>
#include <cuda_bf16.h>
#include <cstdint>

// ---------------------------------------------------------------------------
// Problem constants
// ---------------------------------------------------------------------------
#define NN     100000
#define NE     600000
#define NCEN   512
#define NMOLN  20000
#define NRELS  50
#define D      128
#define NMOT   85

#define OFF_MOTIF (NE * 50)
#define OFF_NODE  (OFF_MOTIF + NCEN * NMOT)
#define OFF_BIN   (OFF_NODE + NMOLN * 15)

// ---------------------------------------------------------------------------
// Device scratch
// ---------------------------------------------------------------------------
__device__ float g_xn   [NN * D];
__device__ float g_x0   [NN * D];
__device__ float g_x1   [NN * D];
__device__ float g_agg  [NN * D];
__device__ float g_elin [NRELS * D];
__device__ float g_proj [NN * 116];
__device__ float g_Wcat [D * 116];
__device__ float g_bcat [116];
__device__ float g_Wfold[D * 116];    // W2 @ Wcat
__device__ float g_bfold[116];        // b2 @ Wcat + bcat
__device__ float g_Wmot [D * NMOT];   // W2 @ motif_W
__device__ float g_bmot [NMOT];       // b2 @ motif_W + motif_b

// ---------------------------------------------------------------------------
// bf16 helpers
// ---------------------------------------------------------------------------
__device__ __forceinline__ uint32_t pack_bf2(float a, float b) {
    __nv_bfloat162 h(__float2bfloat16_rn(a), __float2bfloat16_rn(b));
    return *reinterpret_cast<uint32_t*>(&h);
}
__device__ __forceinline__ float bf_hi(float a) {
    return __bfloat162float(__float2bfloat16_rn(a));
}

// mma.sync m16n8k16 row.col f32.bf16.bf16.f32
#define MMA_BF16(c, a, b0, b1) \
    asm("mma.sync.aligned.m16n8k16.row.col.f32.bf16.bf16.f32 " \
        "{%0,%1,%2,%3}, {%4,%5,%6,%7}, {%8,%9}, {%0,%1,%2,%3};" \
        : "+f"((c)[0]), "+f"((c)[1]), "+f"((c)[2]), "+f"((c)[3]) \
        : "r"((a)[0]), "r"((a)[1]), "r"((a)[2]), "r"((a)[3]), \
          "r"(b0), "r"(b1))

// ---------------------------------------------------------------------------
// HMMA GEMM (proven): Y[r,c] = act( A@W + b ),  K=128, C<=128.
// 3-term bf16 split (ah*bh + ah*bl + al*bh) ~ fp32 accuracy.
// CTA 256 thr = 8 warps (4 row x 2 col), tile 128x128; warp 32x64.
// AMODE: 0 = A1 ; 1 = A1+A2
// BIN: also store column 115 (binary head) to Ybin[row] from the epilogue.
// ---------------------------------------------------------------------------
#define PK 68   // b32 words per staged row (64 data + 4 pad)

template <int C, bool RELU, int AMODE, bool BIN>
__global__ __launch_bounds__(256, 1)
void hgemm_k(const float* __restrict__ A1, const float* __restrict__ A2,
             int nrows,
             const float* __restrict__ W, const float* __restrict__ bias,
             float* __restrict__ Y, float* __restrict__ Ybin) {
    extern __shared__ __align__(16) uint32_t sm32[];
    uint32_t* sAh = sm32;                  // [128][PK]
    uint32_t* sAl = sAh + 128 * PK;
    uint32_t* sBh = sAl + 128 * PK;        // [n][PK] = W^T packed k-pairs
    uint32_t* sBl = sBh + 128 * PK;
    float*  sBias = (float*)(sBl + 128 * PK);   // 128

    const int tid = threadIdx.x;
    const int r0 = blockIdx.x * 128;

    if (tid < 128) sBias[tid] = (tid < C) ? bias[tid] : 0.0f;

    // ---- stage A (hi/lo): 128 rows x 32 float4 ----
    for (int i = tid; i < 128 * 32; i += 256) {
        int r = i >> 5, j = i & 31;
        int gr = r0 + r;
        float4 v = make_float4(0.f, 0.f, 0.f, 0.f);
        if (gr < nrows) {
            if (AMODE == 0) {
                v = reinterpret_cast<const float4*>(A1 + (size_t)gr * D)[j];
            } else {
                float4 a = reinterpret_cast<const float4*>(A1 + (size_t)gr * D)[j];
                float4 b = reinterpret_cast<const float4*>(A2 + (size_t)gr * D)[j];
                v = make_float4(a.x + b.x, a.y + b.y, a.z + b.z, a.w + b.w);
            }
        }
        uint2 hh, ll;
        hh.x = pack_bf2(v.x, v.y);
        hh.y = pack_bf2(v.z, v.w);
        ll.x = pack_bf2(v.x - bf_hi(v.x), v.y - bf_hi(v.y));
        ll.y = pack_bf2(v.z - bf_hi(v.z), v.w - bf_hi(v.w));
        *reinterpret_cast<uint2*>(sAh + r * PK + 2 * j) = hh;
        *reinterpret_cast<uint2*>(sAl + r * PK + 2 * j) = ll;
    }

    // ---- stage B = W^T (hi/lo): sB[n][kp] = (W[2kp][n], W[2kp+1][n]) ----
    for (int i = tid; i < 64 * 128; i += 256) {
        int kp = i >> 7, n = i & 127;   // coalesced along n
        float w0 = 0.f, w1 = 0.f;
        if (n < C) {
            w0 = W[(2 * kp) * C + n];
            w1 = W[(2 * kp + 1) * C + n];
        }
        sBh[n * PK + kp] = pack_bf2(w0, w1);
        sBl[n * PK + kp] = pack_bf2(w0 - bf_hi(w0), w1 - bf_hi(w1));
    }
    __syncthreads();

    // ---- mainloop ----
    const int lane = tid & 31, wid = tid >> 5;
    const int g = lane >> 2, tg = lane & 3;
    const int wm = wid & 3, wn = wid >> 2;

    float acc[2][8][4];
#pragma unroll
    for (int mt = 0; mt < 2; mt++)
#pragma unroll
        for (int nt = 0; nt < 8; nt++)
#pragma unroll
            for (int j = 0; j < 4; j++) acc[mt][nt][j] = 0.f;

    const uint32_t* pA = sAh + (wm * 32 + g) * PK;   // sAl = pA + 128*PK
    const uint32_t* pB = sBh + (wn * 64 + g) * PK;   // sBl = pB + 128*PK

#pragma unroll
    for (int ks = 0; ks < 8; ks++) {
        const int kb = ks * 8 + tg;
        uint32_t ah[2][4], al[2][4];
#pragma unroll
        for (int mt = 0; mt < 2; mt++) {
            const uint32_t* ba = pA + mt * 16 * PK;
            ah[mt][0] = ba[kb];
            ah[mt][1] = ba[8 * PK + kb];
            ah[mt][2] = ba[kb + 4];
            ah[mt][3] = ba[8 * PK + kb + 4];
            const uint32_t* bl_ = ba + 128 * PK;
            al[mt][0] = bl_[kb];
            al[mt][1] = bl_[8 * PK + kb];
            al[mt][2] = bl_[kb + 4];
            al[mt][3] = bl_[8 * PK + kb + 4];
        }
#pragma unroll
        for (int np = 0; np < 4; np++) {
            const int n0 = 2 * np, n1 = 2 * np + 1;
            const uint32_t* bb0 = pB + n0 * 8 * PK;
            const uint32_t* bb1 = pB + n1 * 8 * PK;
            uint32_t bh00 = bb0[kb], bh01 = bb0[kb + 4];
            uint32_t bh10 = bb1[kb], bh11 = bb1[kb + 4];
            uint32_t bl00 = bb0[128 * PK + kb], bl01 = bb0[128 * PK + kb + 4];
            uint32_t bl10 = bb1[128 * PK + kb], bl11 = bb1[128 * PK + kb + 4];

            MMA_BF16(acc[0][n0], ah[0], bh00, bh01);
            MMA_BF16(acc[1][n0], ah[1], bh00, bh01);
            MMA_BF16(acc[0][n1], ah[0], bh10, bh11);
            MMA_BF16(acc[1][n1], ah[1], bh10, bh11);

            MMA_BF16(acc[0][n0], ah[0], bl00, bl01);
            MMA_BF16(acc[1][n0], ah[1], bl00, bl01);
            MMA_BF16(acc[0][n1], ah[0], bl10, bl11);
            MMA_BF16(acc[1][n1], ah[1], bl10, bl11);

            MMA_BF16(acc[0][n0], al[0], bh00, bh01);
            MMA_BF16(acc[1][n0], al[1], bh00, bh01);
            MMA_BF16(acc[0][n1], al[0], bh10, bh11);
            MMA_BF16(acc[1][n1], al[1], bh10, bh11);
        }
    }

    // ---- epilogue: direct global stores (float2 only when C even) ----
#pragma unroll
    for (int mt = 0; mt < 2; mt++) {
#pragma unroll
        for (int nt = 0; nt < 8; nt++) {
            int col = wn * 64 + nt * 8 + tg * 2;
            if (col >= C) continue;
            float b0 = sBias[col];
            float b1 = (col + 1 < C) ? sBias[col + 1] : 0.f;
#pragma unroll
            for (int h = 0; h < 2; h++) {
                int row = r0 + wm * 32 + mt * 16 + g + h * 8;
                if (row >= nrows) continue;
                float v0 = acc[mt][nt][2 * h + 0] + b0;
                float v1 = acc[mt][nt][2 * h + 1] + b1;
                if (RELU) { v0 = fmaxf(v0, 0.f); v1 = fmaxf(v1, 0.f); }
                float* yr = Y + (size_t)row * C + col;
                if ((C & 1) == 0 && col + 1 < C) {
                    *reinterpret_cast<float2*>(yr) = make_float2(v0, v1);
                } else {
                    yr[0] = v0;
                    if (col + 1 < C) yr[1] = v1;
                }
                if (BIN && col + 1 == 115) Ybin[row] = v1;
            }
        }
    }
}

static constexpr int SMEM_HGEMM = (4 * 128 * PK) * 4 + 512;

// ---------------------------------------------------------------------------
// Small-row GEMM: one warp per output row, fp32 exact, K=128, C<=128.
// MODE 0: A = l2norm(A1[row])                (rel-feature path, ridx unused)
// MODE 1: A = A1[ridx[row]] + A2[ridx[row]]  (motif path)
// ---------------------------------------------------------------------------
template <int C, bool RELU, int MODE>
__global__ void sgemm_k(const float* __restrict__ A1, const float* __restrict__ A2,
                        const int* __restrict__ ridx, int n,
                        const float* __restrict__ W, const float* __restrict__ bias,
                        float* __restrict__ Y) {
    int row = (blockIdx.x * blockDim.x + threadIdx.x) >> 5;
    if (row >= n) return;
    int lane = threadIdx.x & 31;
    int gidx = (MODE == 1) ? __ldg(ridx + row) : row;

    float a[4];
#pragma unroll
    for (int j = 0; j < 4; j++) {
        float v = A1[(size_t)gidx * D + lane + 32 * j];
        if (MODE == 1) v += A2[(size_t)gidx * D + lane + 32 * j];
        a[j] = v;
    }
    if (MODE == 0) {
        float ss = a[0] * a[0] + a[1] * a[1] + a[2] * a[2] + a[3] * a[3];
#pragma unroll
        for (int o = 16; o; o >>= 1) ss += __shfl_xor_sync(0xffffffffu, ss, o);
        float inv = 1.0f / fmaxf(sqrtf(ss), 1e-12f);
        a[0] *= inv; a[1] *= inv; a[2] *= inv; a[3] *= inv;
    }

    constexpr int NC = (C + 31) / 32;
    float acc[NC];
#pragma unroll
    for (int jc = 0; jc < NC; jc++) acc[jc] = 0.f;

    for (int k = 0; k < 128; k++) {
        float ak = __shfl_sync(0xffffffffu, a[k >> 5], k & 31);
        const float* wr = W + k * C;
#pragma unroll
        for (int jc = 0; jc < NC; jc++) {
            int c = lane + 32 * jc;
            if (c < C) acc[jc] += ak * __ldg(wr + c);
        }
    }

#pragma unroll
    for (int jc = 0; jc < NC; jc++) {
        int c = lane + 32 * jc;
        if (c < C) {
            float v = acc[jc] + bias[c];
            if (RELU) v = fmaxf(v, 0.f);
            Y[(size_t)row * C + c] = v;
        }
    }
}

// ---------------------------------------------------------------------------
// Gather + L2-normalize rows (one warp per row) — node features.
// ---------------------------------------------------------------------------
__global__ void norm_gather_k(const float* __restrict__ table,
                              const int* __restrict__ ids, int n,
                              float* __restrict__ out) {
    int w = (blockIdx.x * blockDim.x + threadIdx.x) >> 5;
    if (w >= n) return;
    int lane = threadIdx.x & 31;
    int g = ids ? ids[w] : w;
    float4 v = reinterpret_cast<const float4*>(table + (size_t)g * D)[lane];
    float ss = v.x * v.x + v.y * v.y + v.z * v.z + v.w * v.w;
#pragma unroll
    for (int o = 16; o; o >>= 1) ss += __shfl_xor_sync(0xffffffffu, ss, o);
    float inv = 1.0f / fmaxf(sqrtf(ss), 1e-12f);
    v.x *= inv; v.y *= inv; v.z *= inv; v.w *= inv;
    reinterpret_cast<float4*>(out + (size_t)w * D)[lane] = v;
}

// ---------------------------------------------------------------------------
// Message pass: agg[dst] += relu(X[src] + Elin[rel]).  One warp per edge.
// Scatter + RED.v4 (confirmed optimal vs CSR gather [R8] and materialize [R11]).
// ---------------------------------------------------------------------------
__global__ void msg_k(const float* __restrict__ X, const float* __restrict__ Elin,
                      const int* __restrict__ src, const int* __restrict__ dst,
                      const int* __restrict__ rel, float* __restrict__ agg, int nE) {
    int w = (blockIdx.x * blockDim.x + threadIdx.x) >> 5;
    if (w >= nE) return;
    int lane = threadIdx.x & 31;
    int s = __ldg(src + w), d = __ldg(dst + w), r = __ldg(rel + w);
    float4 a = reinterpret_cast<const float4*>(X + (size_t)s * D)[lane];
    float4 b = reinterpret_cast<const float4*>(Elin + (size_t)r * D)[lane];
    float4 m;
    m.x = fmaxf(a.x + b.x, 0.0f);
    m.y = fmaxf(a.y + b.y, 0.0f);
    m.z = fmaxf(a.z + b.z, 0.0f);
    m.w = fmaxf(a.w + b.w, 0.0f);
    atomicAdd(reinterpret_cast<float4*>(agg + (size_t)d * D) + lane, m);
}

__global__ void zero_k(float4* __restrict__ p, int n4) {
    int i = blockIdx.x * blockDim.x + threadIdx.x;
    if (i < n4) p[i] = make_float4(0.f, 0.f, 0.f, 0.f);
}

__global__ void pack_k(const float* __restrict__ eW, const float* __restrict__ ncW,
                       const float* __restrict__ bW, const float* __restrict__ eb,
                       const float* __restrict__ ncb, const float* __restrict__ bb,
                       float* __restrict__ Wcat, float* __restrict__ bcat) {
    int i = blockIdx.x * blockDim.x + threadIdx.x;
    if (i < 128 * 116) {
        int k = i / 116, c = i - k * 116;
        float v;
        if (c < 50)       v = eW[k * 50 + c];
        else if (c < 100) v = eW[(128 + k) * 50 + (c - 50)];
        else if (c < 115) v = ncW[k * 15 + (c - 100)];
        else              v = bW[k];
        Wcat[i] = v;
    }
    if (i < 116) {
        float v;
        if (i < 50)       v = eb[i];
        else if (i < 100) v = 0.0f;
        else if (i < 115) v = ncb[i - 100];
        else              v = bb[0];
        bcat[i] = v;
    }
}

// ---------------------------------------------------------------------------
// Linear-head folding (GINE-2 has no ReLU, so W2 composes with all heads):
//   Wfold = W2 @ Wcat ; bfold = b2 @ Wcat + bcat
//   Wmot  = W2 @ motif_W ; bmot = b2 @ motif_W + motif_b
// ---------------------------------------------------------------------------
#define FOLD_TOTAL (128 * 116 + 116 + 128 * NMOT + NMOT)

__global__ void fold_k(const float* __restrict__ W2, const float* __restrict__ b2,
                       const float* __restrict__ Wcat, const float* __restrict__ bcat,
                       const float* __restrict__ motW, const float* __restrict__ motb,
                       float* __restrict__ Wfold, float* __restrict__ bfold,
                       float* __restrict__ Wmot, float* __restrict__ bmot) {
    int id = blockIdx.x * blockDim.x + threadIdx.x;
    if (id < 128 * 116) {
        int i = id / 116, c = id - i * 116;
        float s = 0.f;
#pragma unroll 4
        for (int j = 0; j < 128; j++) s += W2[i * 128 + j] * Wcat[j * 116 + c];
        Wfold[id] = s;
    } else if (id < 128 * 116 + 116) {
        int c = id - 128 * 116;
        float s = bcat[c];
        for (int j = 0; j < 128; j++) s += b2[j] * Wcat[j * 116 + c];
        bfold[c] = s;
    } else if (id < 128 * 116 + 116 + 128 * NMOT) {
        int t = id - (128 * 116 + 116);
        int i = t / NMOT, m = t - i * NMOT;
        float s = 0.f;
#pragma unroll 4
        for (int j = 0; j < 128; j++) s += W2[i * 128 + j] * motW[j * NMOT + m];
        Wmot[t] = s;
    } else if (id < FOLD_TOTAL) {
        int m = id - (128 * 116 + 116 + 128 * NMOT);
        float s = motb[m];
        for (int j = 0; j < 128; j++) s += b2[j] * motW[j * NMOT + m];
        bmot[m] = s;
    }
}

__global__ void edge_out_k(const float* __restrict__ proj, const int* __restrict__ src,
                           const int* __restrict__ dst, float* __restrict__ out) {
    int i = blockIdx.x * blockDim.x + threadIdx.x;
    if (i >= NE * 25) return;
    int e = i / 25, j = i - e * 25;
    int c = j * 2;
    int s = __ldg(src + e), d = __ldg(dst + e);
    float2 p1 = *reinterpret_cast<const float2*>(proj + (size_t)s * 116 + c);
    float2 p2 = *reinterpret_cast<const float2*>(proj + (size_t)d * 116 + 50 + c);
    *reinterpret_cast<float2*>(out + (size_t)e * 50 + c) =
        make_float2(p1.x + p2.x, p1.y + p2.y);
}

__global__ void node_out_k(const float* __restrict__ proj, const int* __restrict__ ids,
                           float* __restrict__ out) {
    int i = blockIdx.x * blockDim.x + threadIdx.x;
    if (i >= NMOLN * 15) return;
    int m = i / 15, c = i - m * 15;
    out[i] = proj[(size_t)__ldg(ids + m) * 116 + 100 + c];
}

// ---------------------------------------------------------------------------
// Launch
// ---------------------------------------------------------------------------
static inline int cdiv(long long a, long long b) { return (int)((a + b - 1) / b); }

extern "C" void kernel_launch(void* const* d_in, const int* in_sizes, int n_in,
                              void* d_out, int out_size) {
    const int*   node_ids = (const int*)d_in[0];
    const int*   rel_ids  = (const int*)d_in[1];
    const int*   center   = (const int*)d_in[2];
    const int*   nonmol   = (const int*)d_in[3];
    const int*   eidx     = (const int*)d_in[4];
    const float* node_emb = (const float*)d_in[5];
    const float* rel_emb  = (const float*)d_in[6];
    const float* lin_W    = (const float*)d_in[7];
    const float* lin_b    = (const float*)d_in[8];
    const float* W1       = (const float*)d_in[9];
    const float* b1       = (const float*)d_in[10];
    const float* W2       = (const float*)d_in[11];
    const float* b2       = (const float*)d_in[12];
    const float* edge_W   = (const float*)d_in[13];
    const float* edge_b   = (const float*)d_in[14];
    const float* motif_W  = (const float*)d_in[15];
    const float* motif_b  = (const float*)d_in[16];
    const float* nodec_W  = (const float*)d_in[17];
    const float* nodec_b  = (const float*)d_in[18];
    const float* bin_W    = (const float*)d_in[19];
    const float* bin_b    = (const float*)d_in[20];
    const int* src = eidx;
    const int* dst = eidx + NE;
    float* out = (float*)d_out;

    float *xn, *x0, *x1, *agg, *elin, *proj, *Wcat, *bcat;
    float *Wfold, *bfold, *Wmot, *bmot;
    cudaGetSymbolAddress((void**)&xn,    g_xn);
    cudaGetSymbolAddress((void**)&x0,    g_x0);
    cudaGetSymbolAddress((void**)&x1,    g_x1);
    cudaGetSymbolAddress((void**)&agg,   g_agg);
    cudaGetSymbolAddress((void**)&elin,  g_elin);
    cudaGetSymbolAddress((void**)&proj,  g_proj);
    cudaGetSymbolAddress((void**)&Wcat,  g_Wcat);
    cudaGetSymbolAddress((void**)&bcat,  g_bcat);
    cudaGetSymbolAddress((void**)&Wfold, g_Wfold);
    cudaGetSymbolAddress((void**)&bfold, g_bfold);
    cudaGetSymbolAddress((void**)&Wmot,  g_Wmot);
    cudaGetSymbolAddress((void**)&bmot,  g_bmot);

    cudaFuncSetAttribute(hgemm_k<128, true,  0, false>, cudaFuncAttributeMaxDynamicSharedMemorySize, SMEM_HGEMM);
    cudaFuncSetAttribute(hgemm_k<128, true,  1, false>, cudaFuncAttributeMaxDynamicSharedMemorySize, SMEM_HGEMM);
    cudaFuncSetAttribute(hgemm_k<116, false, 1, true>,  cudaFuncAttributeMaxDynamicSharedMemorySize, SMEM_HGEMM);

    const int n4 = NN * D / 4;
    const int gN = cdiv(NN, 128);

    // 1) pack output-head weights, then fold W2 into the linear heads
    pack_k<<<cdiv(128 * 116, 256), 256>>>(edge_W, nodec_W, bin_W, edge_b, nodec_b, bin_b,
                                          Wcat, bcat);
    fold_k<<<cdiv(FOLD_TOTAL, 256), 256>>>(W2, b2, Wcat, bcat, motif_W, motif_b,
                                           Wfold, bfold, Wmot, bmot);
    // 2) rel features: fused l2norm + linear + relu (warp per row, fp32)
    sgemm_k<128, true, 0><<<cdiv((long long)NRELS * 32, 256), 256>>>(
        rel_emb, nullptr, nullptr, NRELS, lin_W, lin_b, elin);
    // 3) node features
    norm_gather_k<<<cdiv((long long)NN * 32, 256), 256>>>(node_emb, node_ids, NN, xn);
    hgemm_k<128, true, 0, false><<<gN, 256, SMEM_HGEMM>>>(xn, nullptr, NN,
                                                          lin_W, lin_b, x0, nullptr);
    // 4) GINE layer 1
    zero_k<<<cdiv(n4, 256), 256>>>((float4*)agg, n4);
    msg_k<<<cdiv((long long)NE * 32, 256), 256>>>(x0, elin, src, dst, rel_ids, agg, NE);
    hgemm_k<128, true, 1, false><<<gN, 256, SMEM_HGEMM>>>(x0, agg, NN,
                                                          W1, b1, x1, nullptr);
    // 5) GINE layer 2 message pass (x2 GEMM folded away)
    zero_k<<<cdiv(n4, 256), 256>>>((float4*)agg, n4);
    msg_k<<<cdiv((long long)NE * 32, 256), 256>>>(x1, elin, src, dst, rel_ids, agg, NE);
    // 6) fused projection from (x1+agg); epilogue also emits the binary head
    hgemm_k<116, false, 1, true><<<gN, 256, SMEM_HGEMM>>>(x1, agg, NN,
                                                          Wfold, bfold, proj,
                                                          out + OFF_BIN);
    // 7) outputs
    edge_out_k<<<cdiv((long long)NE * 25, 256), 256>>>(proj, src, dst, out);
    sgemm_k<85, false, 1><<<cdiv((long long)NCEN * 32, 256), 256>>>(
        x1, agg, center, NCEN, Wmot, bmot, out + OFF_MOTIF);
    node_out_k<<<cdiv((long long)NMOLN * 15, 256), 256>>>(proj, nonmol, out + OFF_NODE);
}

// round 16
// speedup vs baseline: 1.2108x; 1.1646x over previous
#include <cuda_runtime.h>
#include <cuda_bf16.h>
#include <cstdint>

// ---------------------------------------------------------------------------
// Problem constants
// ---------------------------------------------------------------------------
#define NN     100000
#define NE     600000
#define NCEN   512
#define NMOLN  20000
#define NRELS  50
#define D      128
#define NMOT   85

#define OFF_MOTIF (NE * 50)
#define OFF_NODE  (OFF_MOTIF + NCEN * NMOT)
#define OFF_BIN   (OFF_NODE + NMOLN * 15)

// ---------------------------------------------------------------------------
// Device scratch
// ---------------------------------------------------------------------------
__device__ float g_xn   [NN * D];
__device__ float g_x0   [NN * D];
__device__ float g_x1   [NN * D];
__device__ float g_agg  [NN * D];
__device__ float g_elin [NRELS * D];
__device__ float g_proj [NN * 116];
__device__ float g_Wcat [D * 116];
__device__ float g_bcat [116];
__device__ float g_Wfold[D * 116];    // W2 @ Wcat
__device__ float g_bfold[116];        // b2 @ Wcat + bcat
__device__ float g_Wmot [D * NMOT];   // W2 @ motif_W
__device__ float g_bmot [NMOT];       // b2 @ motif_W + motif_b

// ---------------------------------------------------------------------------
// bf16 helpers
// ---------------------------------------------------------------------------
__device__ __forceinline__ uint32_t pack_bf2(float a, float b) {
    __nv_bfloat162 h(__float2bfloat16_rn(a), __float2bfloat16_rn(b));
    return *reinterpret_cast<uint32_t*>(&h);
}
__device__ __forceinline__ float bf_hi(float a) {
    return __bfloat162float(__float2bfloat16_rn(a));
}

// mma.sync m16n8k16 row.col f32.bf16.bf16.f32
#define MMA_BF16(c, a, b0, b1) \
    asm("mma.sync.aligned.m16n8k16.row.col.f32.bf16.bf16.f32 " \
        "{%0,%1,%2,%3}, {%4,%5,%6,%7}, {%8,%9}, {%0,%1,%2,%3};" \
        : "+f"((c)[0]), "+f"((c)[1]), "+f"((c)[2]), "+f"((c)[3]) \
        : "r"((a)[0]), "r"((a)[1]), "r"((a)[2]), "r"((a)[3]), \
          "r"(b0), "r"(b1))

// ---------------------------------------------------------------------------
// HMMA GEMM, 64-row tile / 2 CTAs per SM: Y[r,c] = act( A@W + b ), K=128, C<=128.
// 3-term bf16 split (ah*bh + ah*bl + al*bh) ~ fp32 accuracy.
// CTA 256 thr = 8 warps (4 row-warps x 16 rows, 2 col-warps x 64 cols).
// SMEM ~105 KB -> 2 CTAs/SM = 16 warps/SM (vs 8 in the 128-row version).
// AMODE: 0 = A1 ; 1 = A1+A2
// BIN: also store column 115 (binary head) to Ybin[row] from the epilogue.
// ---------------------------------------------------------------------------
#define PK 68   // b32 words per staged row (64 data + 4 pad)
#define TM 64   // tile rows

template <int C, bool RELU, int AMODE, bool BIN>
__global__ __launch_bounds__(256, 2)
void hgemm_k(const float* __restrict__ A1, const float* __restrict__ A2,
             int nrows,
             const float* __restrict__ W, const float* __restrict__ bias,
             float* __restrict__ Y, float* __restrict__ Ybin) {
    extern __shared__ __align__(16) uint32_t sm32[];
    uint32_t* sAh = sm32;                    // [TM][PK]
    uint32_t* sAl = sAh + TM * PK;           // [TM][PK]
    uint32_t* sBh = sAl + TM * PK;           // [128][PK]
    uint32_t* sBl = sBh + 128 * PK;          // [128][PK]
    float*  sBias = (float*)(sBl + 128 * PK);   // 128

    const int tid = threadIdx.x;
    const int r0 = blockIdx.x * TM;

    if (tid < 128) sBias[tid] = (tid < C) ? bias[tid] : 0.0f;

    // ---- stage A (hi/lo): TM rows x 32 float4 ----
    for (int i = tid; i < TM * 32; i += 256) {
        int r = i >> 5, j = i & 31;
        int gr = r0 + r;
        float4 v = make_float4(0.f, 0.f, 0.f, 0.f);
        if (gr < nrows) {
            if (AMODE == 0) {
                v = reinterpret_cast<const float4*>(A1 + (size_t)gr * D)[j];
            } else {
                float4 a = reinterpret_cast<const float4*>(A1 + (size_t)gr * D)[j];
                float4 b = reinterpret_cast<const float4*>(A2 + (size_t)gr * D)[j];
                v = make_float4(a.x + b.x, a.y + b.y, a.z + b.z, a.w + b.w);
            }
        }
        uint2 hh, ll;
        hh.x = pack_bf2(v.x, v.y);
        hh.y = pack_bf2(v.z, v.w);
        ll.x = pack_bf2(v.x - bf_hi(v.x), v.y - bf_hi(v.y));
        ll.y = pack_bf2(v.z - bf_hi(v.z), v.w - bf_hi(v.w));
        *reinterpret_cast<uint2*>(sAh + r * PK + 2 * j) = hh;
        *reinterpret_cast<uint2*>(sAl + r * PK + 2 * j) = ll;
    }

    // ---- stage B = W^T (hi/lo): sB[n][kp] = (W[2kp][n], W[2kp+1][n]) ----
    for (int i = tid; i < 64 * 128; i += 256) {
        int kp = i >> 7, n = i & 127;   // coalesced along n
        float w0 = 0.f, w1 = 0.f;
        if (n < C) {
            w0 = W[(2 * kp) * C + n];
            w1 = W[(2 * kp + 1) * C + n];
        }
        sBh[n * PK + kp] = pack_bf2(w0, w1);
        sBl[n * PK + kp] = pack_bf2(w0 - bf_hi(w0), w1 - bf_hi(w1));
    }
    __syncthreads();

    // ---- mainloop ----
    const int lane = tid & 31, wid = tid >> 5;
    const int g = lane >> 2, tg = lane & 3;
    const int wm = wid & 3, wn = wid >> 2;   // 4 row-warps x 2 col-warps

    float acc[8][4];
#pragma unroll
    for (int nt = 0; nt < 8; nt++)
#pragma unroll
        for (int j = 0; j < 4; j++) acc[nt][j] = 0.f;

    const uint32_t* pA = sAh + (wm * 16 + g) * PK;   // sAl = pA + TM*PK
    const uint32_t* pB = sBh + (wn * 64 + g) * PK;   // sBl = pB + 128*PK

#pragma unroll
    for (int ks = 0; ks < 8; ks++) {
        const int kb = ks * 8 + tg;
        uint32_t ah[4], al[4];
        ah[0] = pA[kb];
        ah[1] = pA[8 * PK + kb];
        ah[2] = pA[kb + 4];
        ah[3] = pA[8 * PK + kb + 4];
        const uint32_t* pAl = pA + TM * PK;
        al[0] = pAl[kb];
        al[1] = pAl[8 * PK + kb];
        al[2] = pAl[kb + 4];
        al[3] = pAl[8 * PK + kb + 4];
#pragma unroll
        for (int np = 0; np < 4; np++) {
            const int n0 = 2 * np, n1 = 2 * np + 1;
            const uint32_t* bb0 = pB + n0 * 8 * PK;
            const uint32_t* bb1 = pB + n1 * 8 * PK;
            uint32_t bh00 = bb0[kb], bh01 = bb0[kb + 4];
            uint32_t bh10 = bb1[kb], bh11 = bb1[kb + 4];
            uint32_t bl00 = bb0[128 * PK + kb], bl01 = bb0[128 * PK + kb + 4];
            uint32_t bl10 = bb1[128 * PK + kb], bl11 = bb1[128 * PK + kb + 4];

            MMA_BF16(acc[n0], ah, bh00, bh01);
            MMA_BF16(acc[n1], ah, bh10, bh11);
            MMA_BF16(acc[n0], ah, bl00, bl01);
            MMA_BF16(acc[n1], ah, bl10, bl11);
            MMA_BF16(acc[n0], al, bh00, bh01);
            MMA_BF16(acc[n1], al, bh10, bh11);
        }
    }

    // ---- epilogue: direct global stores (float2 only when C even) ----
#pragma unroll
    for (int nt = 0; nt < 8; nt++) {
        int col = wn * 64 + nt * 8 + tg * 2;
        if (col >= C) continue;
        float b0 = sBias[col];
        float b1 = (col + 1 < C) ? sBias[col + 1] : 0.f;
#pragma unroll
        for (int h = 0; h < 2; h++) {
            int row = r0 + wm * 16 + g + h * 8;
            if (row >= nrows) continue;
            float v0 = acc[nt][2 * h + 0] + b0;
            float v1 = acc[nt][2 * h + 1] + b1;
            if (RELU) { v0 = fmaxf(v0, 0.f); v1 = fmaxf(v1, 0.f); }
            float* yr = Y + (size_t)row * C + col;
            if ((C & 1) == 0 && col + 1 < C) {
                *reinterpret_cast<float2*>(yr) = make_float2(v0, v1);
            } else {
                yr[0] = v0;
                if (col + 1 < C) yr[1] = v1;
            }
            if (BIN && col + 1 == 115) Ybin[row] = v1;
        }
    }
}

static constexpr int SMEM_HGEMM = (2 * TM * PK + 2 * 128 * PK) * 4 + 512;

// ---------------------------------------------------------------------------
// Small-row GEMM: one warp per output row, fp32 exact, K=128, C<=128.
// MODE 0: A = l2norm(A1[row])                (rel-feature path, ridx unused)
// MODE 1: A = A1[ridx[row]] + A2[ridx[row]]  (motif path)
// ---------------------------------------------------------------------------
template <int C, bool RELU, int MODE>
__global__ void sgemm_k(const float* __restrict__ A1, const float* __restrict__ A2,
                        const int* __restrict__ ridx, int n,
                        const float* __restrict__ W, const float* __restrict__ bias,
                        float* __restrict__ Y) {
    int row = (blockIdx.x * blockDim.x + threadIdx.x) >> 5;
    if (row >= n) return;
    int lane = threadIdx.x & 31;
    int gidx = (MODE == 1) ? __ldg(ridx + row) : row;

    float a[4];
#pragma unroll
    for (int j = 0; j < 4; j++) {
        float v = A1[(size_t)gidx * D + lane + 32 * j];
        if (MODE == 1) v += A2[(size_t)gidx * D + lane + 32 * j];
        a[j] = v;
    }
    if (MODE == 0) {
        float ss = a[0] * a[0] + a[1] * a[1] + a[2] * a[2] + a[3] * a[3];
#pragma unroll
        for (int o = 16; o; o >>= 1) ss += __shfl_xor_sync(0xffffffffu, ss, o);
        float inv = 1.0f / fmaxf(sqrtf(ss), 1e-12f);
        a[0] *= inv; a[1] *= inv; a[2] *= inv; a[3] *= inv;
    }

    constexpr int NC = (C + 31) / 32;
    float acc[NC];
#pragma unroll
    for (int jc = 0; jc < NC; jc++) acc[jc] = 0.f;

    for (int k = 0; k < 128; k++) {
        float ak = __shfl_sync(0xffffffffu, a[k >> 5], k & 31);
        const float* wr = W + k * C;
#pragma unroll
        for (int jc = 0; jc < NC; jc++) {
            int c = lane + 32 * jc;
            if (c < C) acc[jc] += ak * __ldg(wr + c);
        }
    }

#pragma unroll
    for (int jc = 0; jc < NC; jc++) {
        int c = lane + 32 * jc;
        if (c < C) {
            float v = acc[jc] + bias[c];
            if (RELU) v = fmaxf(v, 0.f);
            Y[(size_t)row * C + c] = v;
        }
    }
}

// ---------------------------------------------------------------------------
// Gather + L2-normalize rows (one warp per row) — node features.
// ---------------------------------------------------------------------------
__global__ void norm_gather_k(const float* __restrict__ table,
                              const int* __restrict__ ids, int n,
                              float* __restrict__ out) {
    int w = (blockIdx.x * blockDim.x + threadIdx.x) >> 5;
    if (w >= n) return;
    int lane = threadIdx.x & 31;
    int g = ids ? ids[w] : w;
    float4 v = reinterpret_cast<const float4*>(table + (size_t)g * D)[lane];
    float ss = v.x * v.x + v.y * v.y + v.z * v.z + v.w * v.w;
#pragma unroll
    for (int o = 16; o; o >>= 1) ss += __shfl_xor_sync(0xffffffffu, ss, o);
    float inv = 1.0f / fmaxf(sqrtf(ss), 1e-12f);
    v.x *= inv; v.y *= inv; v.z *= inv; v.w *= inv;
    reinterpret_cast<float4*>(out + (size_t)w * D)[lane] = v;
}

// ---------------------------------------------------------------------------
// Message pass: agg[dst] += relu(X[src] + Elin[rel]).  One warp per edge.
// Scatter + RED.v4 (confirmed optimal vs CSR gather [R8] and materialize [R11]).
// ---------------------------------------------------------------------------
__global__ void msg_k(const float* __restrict__ X, const float* __restrict__ Elin,
                      const int* __restrict__ src, const int* __restrict__ dst,
                      const int* __restrict__ rel, float* __restrict__ agg, int nE) {
    int w = (blockIdx.x * blockDim.x + threadIdx.x) >> 5;
    if (w >= nE) return;
    int lane = threadIdx.x & 31;
    int s = __ldg(src + w), d = __ldg(dst + w), r = __ldg(rel + w);
    float4 a = reinterpret_cast<const float4*>(X + (size_t)s * D)[lane];
    float4 b = reinterpret_cast<const float4*>(Elin + (size_t)r * D)[lane];
    float4 m;
    m.x = fmaxf(a.x + b.x, 0.0f);
    m.y = fmaxf(a.y + b.y, 0.0f);
    m.z = fmaxf(a.z + b.z, 0.0f);
    m.w = fmaxf(a.w + b.w, 0.0f);
    atomicAdd(reinterpret_cast<float4*>(agg + (size_t)d * D) + lane, m);
}

__global__ void zero_k(float4* __restrict__ p, int n4) {
    int i = blockIdx.x * blockDim.x + threadIdx.x;
    if (i < n4) p[i] = make_float4(0.f, 0.f, 0.f, 0.f);
}

__global__ void pack_k(const float* __restrict__ eW, const float* __restrict__ ncW,
                       const float* __restrict__ bW, const float* __restrict__ eb,
                       const float* __restrict__ ncb, const float* __restrict__ bb,
                       float* __restrict__ Wcat, float* __restrict__ bcat) {
    int i = blockIdx.x * blockDim.x + threadIdx.x;
    if (i < 128 * 116) {
        int k = i / 116, c = i - k * 116;
        float v;
        if (c < 50)       v = eW[k * 50 + c];
        else if (c < 100) v = eW[(128 + k) * 50 + (c - 50)];
        else if (c < 115) v = ncW[k * 15 + (c - 100)];
        else              v = bW[k];
        Wcat[i] = v;
    }
    if (i < 116) {
        float v;
        if (i < 50)       v = eb[i];
        else if (i < 100) v = 0.0f;
        else if (i < 115) v = ncb[i - 100];
        else              v = bb[0];
        bcat[i] = v;
    }
}

// ---------------------------------------------------------------------------
// Linear-head folding (GINE-2 has no ReLU, so W2 composes with all heads):
//   Wfold = W2 @ Wcat ; bfold = b2 @ Wcat + bcat
//   Wmot  = W2 @ motif_W ; bmot = b2 @ motif_W + motif_b
// ---------------------------------------------------------------------------
#define FOLD_TOTAL (128 * 116 + 116 + 128 * NMOT + NMOT)

__global__ void fold_k(const float* __restrict__ W2, const float* __restrict__ b2,
                       const float* __restrict__ Wcat, const float* __restrict__ bcat,
                       const float* __restrict__ motW, const float* __restrict__ motb,
                       float* __restrict__ Wfold, float* __restrict__ bfold,
                       float* __restrict__ Wmot, float* __restrict__ bmot) {
    int id = blockIdx.x * blockDim.x + threadIdx.x;
    if (id < 128 * 116) {
        int i = id / 116, c = id - i * 116;
        float s = 0.f;
#pragma unroll 4
        for (int j = 0; j < 128; j++) s += W2[i * 128 + j] * Wcat[j * 116 + c];
        Wfold[id] = s;
    } else if (id < 128 * 116 + 116) {
        int c = id - 128 * 116;
        float s = bcat[c];
        for (int j = 0; j < 128; j++) s += b2[j] * Wcat[j * 116 + c];
        bfold[c] = s;
    } else if (id < 128 * 116 + 116 + 128 * NMOT) {
        int t = id - (128 * 116 + 116);
        int i = t / NMOT, m = t - i * NMOT;
        float s = 0.f;
#pragma unroll 4
        for (int j = 0; j < 128; j++) s += W2[i * 128 + j] * motW[j * NMOT + m];
        Wmot[t] = s;
    } else if (id < FOLD_TOTAL) {
        int m = id - (128 * 116 + 116 + 128 * NMOT);
        float s = motb[m];
        for (int j = 0; j < 128; j++) s += b2[j] * motW[j * NMOT + m];
        bmot[m] = s;
    }
}

__global__ void edge_out_k(const float* __restrict__ proj, const int* __restrict__ src,
                           const int* __restrict__ dst, float* __restrict__ out) {
    int i = blockIdx.x * blockDim.x + threadIdx.x;
    if (i >= NE * 25) return;
    int e = i / 25, j = i - e * 25;
    int c = j * 2;
    int s = __ldg(src + e), d = __ldg(dst + e);
    float2 p1 = *reinterpret_cast<const float2*>(proj + (size_t)s * 116 + c);
    float2 p2 = *reinterpret_cast<const float2*>(proj + (size_t)d * 116 + 50 + c);
    *reinterpret_cast<float2*>(out + (size_t)e * 50 + c) =
        make_float2(p1.x + p2.x, p1.y + p2.y);
}

__global__ void node_out_k(const float* __restrict__ proj, const int* __restrict__ ids,
                           float* __restrict__ out) {
    int i = blockIdx.x * blockDim.x + threadIdx.x;
    if (i >= NMOLN * 15) return;
    int m = i / 15, c = i - m * 15;
    out[i] = proj[(size_t)__ldg(ids + m) * 116 + 100 + c];
}

// ---------------------------------------------------------------------------
// Launch
// ---------------------------------------------------------------------------
static inline int cdiv(long long a, long long b) { return (int)((a + b - 1) / b); }

extern "C" void kernel_launch(void* const* d_in, const int* in_sizes, int n_in,
                              void* d_out, int out_size) {
    const int*   node_ids = (const int*)d_in[0];
    const int*   rel_ids  = (const int*)d_in[1];
    const int*   center   = (const int*)d_in[2];
    const int*   nonmol   = (const int*)d_in[3];
    const int*   eidx     = (const int*)d_in[4];
    const float* node_emb = (const float*)d_in[5];
    const float* rel_emb  = (const float*)d_in[6];
    const float* lin_W    = (const float*)d_in[7];
    const float* lin_b    = (const float*)d_in[8];
    const float* W1       = (const float*)d_in[9];
    const float* b1       = (const float*)d_in[10];
    const float* W2       = (const float*)d_in[11];
    const float* b2       = (const float*)d_in[12];
    const float* edge_W   = (const float*)d_in[13];
    const float* edge_b   = (const float*)d_in[14];
    const float* motif_W  = (const float*)d_in[15];
    const float* motif_b  = (const float*)d_in[16];
    const float* nodec_W  = (const float*)d_in[17];
    const float* nodec_b  = (const float*)d_in[18];
    const float* bin_W    = (const float*)d_in[19];
    const float* bin_b    = (const float*)d_in[20];
    const int* src = eidx;
    const int* dst = eidx + NE;
    float* out = (float*)d_out;

    float *xn, *x0, *x1, *agg, *elin, *proj, *Wcat, *bcat;
    float *Wfold, *bfold, *Wmot, *bmot;
    cudaGetSymbolAddress((void**)&xn,    g_xn);
    cudaGetSymbolAddress((void**)&x0,    g_x0);
    cudaGetSymbolAddress((void**)&x1,    g_x1);
    cudaGetSymbolAddress((void**)&agg,   g_agg);
    cudaGetSymbolAddress((void**)&elin,  g_elin);
    cudaGetSymbolAddress((void**)&proj,  g_proj);
    cudaGetSymbolAddress((void**)&Wcat,  g_Wcat);
    cudaGetSymbolAddress((void**)&bcat,  g_bcat);
    cudaGetSymbolAddress((void**)&Wfold, g_Wfold);
    cudaGetSymbolAddress((void**)&bfold, g_bfold);
    cudaGetSymbolAddress((void**)&Wmot,  g_Wmot);
    cudaGetSymbolAddress((void**)&bmot,  g_bmot);

    cudaFuncSetAttribute(hgemm_k<128, true,  0, false>, cudaFuncAttributeMaxDynamicSharedMemorySize, SMEM_HGEMM);
    cudaFuncSetAttribute(hgemm_k<128, true,  1, false>, cudaFuncAttributeMaxDynamicSharedMemorySize, SMEM_HGEMM);
    cudaFuncSetAttribute(hgemm_k<116, false, 1, true>,  cudaFuncAttributeMaxDynamicSharedMemorySize, SMEM_HGEMM);

    const int n4 = NN * D / 4;
    const int gN = cdiv(NN, TM);

    // 1) pack output-head weights, then fold W2 into the linear heads
    pack_k<<<cdiv(128 * 116, 256), 256>>>(edge_W, nodec_W, bin_W, edge_b, nodec_b, bin_b,
                                          Wcat, bcat);
    fold_k<<<cdiv(FOLD_TOTAL, 256), 256>>>(W2, b2, Wcat, bcat, motif_W, motif_b,
                                           Wfold, bfold, Wmot, bmot);
    // 2) rel features: fused l2norm + linear + relu (warp per row, fp32)
    sgemm_k<128, true, 0><<<cdiv((long long)NRELS * 32, 256), 256>>>(
        rel_emb, nullptr, nullptr, NRELS, lin_W, lin_b, elin);
    // 3) node features
    norm_gather_k<<<cdiv((long long)NN * 32, 256), 256>>>(node_emb, node_ids, NN, xn);
    hgemm_k<128, true, 0, false><<<gN, 256, SMEM_HGEMM>>>(xn, nullptr, NN,
                                                          lin_W, lin_b, x0, nullptr);
    // 4) GINE layer 1
    zero_k<<<cdiv(n4, 256), 256>>>((float4*)agg, n4);
    msg_k<<<cdiv((long long)NE * 32, 256), 256>>>(x0, elin, src, dst, rel_ids, agg, NE);
    hgemm_k<128, true, 1, false><<<gN, 256, SMEM_HGEMM>>>(x0, agg, NN,
                                                          W1, b1, x1, nullptr);
    // 5) GINE layer 2 message pass (x2 GEMM folded away)
    zero_k<<<cdiv(n4, 256), 256>>>((float4*)agg, n4);
    msg_k<<<cdiv((long long)NE * 32, 256), 256>>>(x1, elin, src, dst, rel_ids, agg, NE);
    // 6) fused projection from (x1+agg); epilogue also emits the binary head
    hgemm_k<116, false, 1, true><<<gN, 256, SMEM_HGEMM>>>(x1, agg, NN,
                                                          Wfold, bfold, proj,
                                                          out + OFF_BIN);
    // 7) outputs
    edge_out_k<<<cdiv((long long)NE * 25, 256), 256>>>(proj, src, dst, out);
    sgemm_k<85, false, 1><<<cdiv((long long)NCEN * 32, 256), 256>>>(
        x1, agg, center, NCEN, Wmot, bmot, out + OFF_MOTIF);
    node_out_k<<<cdiv((long long)NMOLN * 15, 256), 256>>>(proj, nonmol, out + OFF_NODE);
}